// round 14
// baseline (speedup 1.0000x reference)
#include <cuda_runtime.h>
#include <stdint.h>

#define NB    8
#define NMEL  80
#define NT    512
#define NF    401
#define NFFT  800
#define LOUT  102200
#define LPAD  103000
#define ROWS  4096
#define NTOT  1642496     /* ROWS*NF  */
#define FRTOT 3276800     /* ROWS*NFFT */
#define FRB   4           /* frames per block in CT kernels */
#define KPAD  416         /* padded k extent: 32*13 */
#define BW    24          /* mel filter band width (max ~22 nonzeros) */
#define MROWS 8           /* rows per block in mega-mel */

// ------------------------- device scratch (no allocs) ------------------------
__device__ float  g_fb  [NF*NMEL];
__device__ float  g_fbT [NMEL*NF];
__device__ float  g_win [NFFT];
__device__ double g_twcD[NFFT];
__device__ double g_twsD[NFFT];
__device__ float  g_wsqi[LPAD];
__device__ float2 g_TI  [25][KPAD];  // (w/800)·(cos,sin)(2pi k q/800), 0 pad
__device__ float2 g_TF  [25][KPAD];  // (cos,sin)(2pi k q/800), 0 pad
__device__ float2 g_cs32[32][17];    // (cos,sin)(2pi a b/32)
__device__ int    g_klo [NMEL];      // first nonzero k of fb column m
__device__ float  g_fbc [NMEL][BW];  // fb[klo+j][m], zero-padded
__device__ int    g_ms  [NF];        // first nonzero m of fbT column f
__device__ float  g_fbv [NF][4];     // fbT[ms+j][f], zero-padded
__device__ float  g_spec[NTOT];
__device__ float  g_mag [NTOT];
__device__ float2 g_ang [NTOT];      // (angR, angI)
__device__ float2 g_t   [NTOT];      // (tR, tI)
__device__ float  g_fr  [FRTOT];
__device__ float  g_inv [NB*LOUT];
__device__ float  g_peak[NB];

// ------------------------- threefry-2x32 (JAX schedule) ----------------------
__host__ __device__ inline void tf_block(unsigned k0, unsigned k1,
                                         unsigned c0, unsigned c1,
                                         unsigned &o0, unsigned &o1){
  unsigned ks2 = k0 ^ k1 ^ 0x1BD11BDAu;
  unsigned x0 = c0 + k0, x1 = c1 + k1;
#define TFR(r) { x0 += x1; x1 = (x1 << (r)) | (x1 >> (32 - (r))); x1 ^= x0; }
  TFR(13) TFR(15) TFR(26) TFR(6)  x0 += k1;  x1 += ks2 + 1u;
  TFR(17) TFR(29) TFR(16) TFR(24) x0 += ks2; x1 += k0 + 2u;
  TFR(13) TFR(15) TFR(26) TFR(6)  x0 += k0;  x1 += k1 + 3u;
  TFR(17) TFR(29) TFR(16) TFR(24) x0 += k1;  x1 += ks2 + 4u;
  TFR(13) TFR(15) TFR(26) TFR(6)  x0 += ks2; x1 += k0 + 5u;
#undef TFR
  o0 = x0; o1 = x1;
}

__device__ __forceinline__ float u01(unsigned bits){
  return __uint_as_float((bits >> 9) | 0x3f800000u) - 1.0f;
}

// ------------------------- setup kernels ------------------------------------
__global__ void k_setup1(){
  int i = blockIdx.x*blockDim.x + threadIdx.x;
  if (i < NFFT){
    g_win[i]  = (float)(0.5 - 0.5*cospi((double)i/400.0));
    g_twcD[i] = cospi((double)i/400.0);
    g_twsD[i] = sinpi((double)i/400.0);
  }
  if (i < NF*NMEL){
    int f = i / NMEL, m = i - f*NMEL;
    double freq = 10.0 * f;
    double mmax = 2595.0 * log10(1.0 + 4000.0/700.0);
    double p0 = 700.0*(pow(10.0, (mmax*(double)(m  )/81.0)/2595.0) - 1.0);
    double p1 = 700.0*(pow(10.0, (mmax*(double)(m+1)/81.0)/2595.0) - 1.0);
    double p2 = 700.0*(pow(10.0, (mmax*(double)(m+2)/81.0)/2595.0) - 1.0);
    double down = (freq - p0) / (p1 - p0);
    double up   = (p2 - freq) / (p2 - p1);
    double v = fmax(0.0, fmin(down, up));
    g_fb [f*NMEL + m] = (float)v;
    g_fbT[m*NF  + f] = (float)v;
  }
}

#define SET2_TOT (LPAD + 25*KPAD + 32*17 + NMEL + NF)
__global__ void k_setup2(){
  int i = blockIdx.x*blockDim.x + threadIdx.x;
  if (i < LPAD){
    int j = i;
    int tlo = (j >= 600) ? (j-600)/200 : 0;
    int thi = j/200; if (thi > 511) thi = 511;
    double s = 0.0;
    for (int t = tlo; t <= thi; t++){
      double w = (double)g_win[j - 200*t];
      s += w*w;
    }
    s = fmax(s, 1e-11);
    g_wsqi[j] = (float)(1.0 / s);
    return;
  }
  int ib = i - LPAD;
  if (ib < 25*KPAD){
    int q = ib / KPAD, k = ib - q*KPAD;
    if (k < NF){
      int r = (k*q) % 800;
      double c = g_twcD[r], s = g_twsD[r];
      double w = (k == 0 || k == 400) ? 1.0 : 2.0;
      g_TI[q][k] = make_float2((float)(w/800.0 * c), (float)(w/800.0 * s));
      g_TF[q][k] = make_float2((float)c, (float)s);
    } else {
      g_TI[q][k] = make_float2(0.f, 0.f);
      g_TF[q][k] = make_float2(0.f, 0.f);
    }
    return;
  }
  int ic = ib - 25*KPAD;
  if (ic < 32*17){
    int a = ic / 17, b = ic - 17*a;
    int r = (a*b) % 32;
    g_cs32[a][b] = make_float2((float)cospi((double)r/16.0),
                               (float)sinpi((double)r/16.0));
    return;
  }
  int id = ic - 32*17;
  if (id < NMEL){
    int m = id;
    int klo = 0;
    for (int k = 0; k < NF; k++)
      if (g_fb[k*NMEL + m] > 0.f){ klo = k; break; }
    g_klo[m] = klo;
    for (int j = 0; j < BW; j++){
      int k = klo + j;
      g_fbc[m][j] = (k < NF) ? g_fb[k*NMEL + m] : 0.f;
    }
    return;
  }
  int ie = id - NMEL;
  if (ie < NF){
    int f = ie;
    int ms = 0;
    for (int m = 0; m < NMEL; m++)
      if (g_fbT[m*NF + f] > 0.f){ ms = m; break; }
    g_ms[f] = ms;
    for (int j = 0; j < 4; j++){
      int m = ms + j;
      g_fbv[f][j] = (m < NMEL) ? g_fbT[m*NF + f] : 0.f;
    }
  }
}

// ------------------------- RNG init ------------------------------------------
__global__ void k_init(unsigned a0, unsigned a1, unsigned r0, unsigned r1,
                       unsigned q0, unsigned q1){
  int i = blockIdx.x*blockDim.x + threadIdx.x;
  if (i >= NTOT) return;
  unsigned o0, o1;
  tf_block(a0, a1, 0u, (unsigned)i, o0, o1);
  g_spec[i] = u01(o0 ^ o1);                     // spec0 is (B,T,F) = our layout
  g_t[i] = make_float2(0.f, 0.f);
  // angles drawn in (B,F,T) order -> remap flat index
  int b = i / (NT*NF);
  int rem = i - b*(NT*NF);
  int t = rem / NF, f = rem - t*NF;
  unsigned j = (unsigned)(b*(NF*NT) + f*NT + t);
  unsigned p0, p1;
  tf_block(r0, r1, 0u, j, o0, o1);
  tf_block(q0, q1, 0u, j, p0, p1);
  g_ang[i] = make_float2(u01(o0 ^ o1), u01(p0 ^ p1));
}

// ------------------------- mega mel (R12: transposed tables) -----------------
struct MelS {
  float sS[MROWS][440];   // spec rows, zero-padded k>=401
  float vS[MROWS][404];   // velocity
  float dS[MROWS][84];    // diff, zero-padded m>=80
  float xS[MROWS][80];    // mel target (cached)
  float fbcT[BW][80];     // transposed: stride-1 lane access
  float fbvT[4][404];
  int   klo[NMEL];
  int   ms[NF];
};

__global__ __launch_bounds__(256)
void k_mel50(const float* __restrict__ x){
  extern __shared__ char smraw[];
  MelS* S = (MelS*)smraw;
  const int tid = threadIdx.x;
  const int row0 = blockIdx.x * MROWS;

  for (int i = tid; i < MROWS*440; i += 256){
    int r = i / 440, k = i - r*440;
    S->sS[r][k] = (k < NF) ? g_spec[(row0 + r)*NF + k] : 0.f;
  }
  for (int i = tid; i < MROWS*404; i += 256){
    int r = i / 404, k = i - r*404;
    S->vS[r][k] = 0.f;
  }
  for (int i = tid; i < MROWS*84; i += 256){
    int r = i / 84, m = i - r*84;
    if (m >= NMEL) S->dS[r][m] = 0.f;
  }
  for (int i = tid; i < MROWS*NMEL; i += 256){
    int r = i / NMEL, m = i - r*NMEL;
    int row = row0 + r, b = row >> 9, t = row & 511;
    S->xS[r][m] = x[(b*NMEL + m)*NT + t];
  }
  for (int i = tid; i < NMEL*BW; i += 256){
    int m = i / BW, j = i - m*BW;
    S->fbcT[j][m] = g_fbc[m][j];
  }
  for (int i = tid; i < NF*4; i += 256){
    int f = i >> 2, j = i & 3;
    S->fbvT[j][f] = g_fbv[f][j];
  }
  for (int i = tid; i < NMEL; i += 256) S->klo[i] = g_klo[i];
  for (int i = tid; i < NF;   i += 256) S->ms[i]  = g_ms[i];
  __syncthreads();

#pragma unroll 1
  for (int it = 0; it < 50; it++){
    for (int i = tid; i < MROWS*NMEL; i += 256){
      int r = i / NMEL, m = i - r*NMEL;
      int klo = S->klo[m];
      float acc = 0.f;
#pragma unroll
      for (int j = 0; j < BW; j++)
        acc = fmaf(S->sS[r][klo + j], S->fbcT[j][m], acc);
      S->dS[r][m] = S->xS[r][m] - acc;
    }
    __syncthreads();
    for (int i = tid; i < MROWS*NF; i += 256){
      int r = i / NF, f = i - r*NF;
      int ms = S->ms[f];
      float acc = 0.f;
#pragma unroll
      for (int j = 0; j < 4; j++)
        acc = fmaf(S->dS[r][ms + j], S->fbvT[j][f], acc);
      float g = -0.003125f * acc;             // -2/(B*M)
      float v = 0.9f * S->vS[r][f] + g;
      S->vS[r][f] = v;
      S->sS[r][f] = fmaxf(S->sS[r][f] - 0.1f*v, 0.f);
    }
    __syncthreads();
  }

  for (int i = tid; i < MROWS*NF; i += 256){
    int r = i / NF, k = i - r*NF;
    g_mag[(row0 + r)*NF + k] = sqrtf(S->sS[r][k]);
  }
}

// ------------------------- CT istft (frame-contiguous P: LDS.128 over f) -----
struct __align__(16) IstftS {
  union {
    float2 P [KPAD][FRB];          // (Pre,Pim), f contiguous  13.3 KB
    float2 AB[FRB][17][25];        // (Aa, Bb)                 13.6 KB
  } u;
  float2 H [FRB][25][32];          // (Hr, Hi)                 25.6 KB
  float2 cs[32][17];               // (c32, s32)                4.3 KB
};

__global__ __launch_bounds__(256)
void k_istft(){
  __shared__ IstftS S;
  const int tid = threadIdx.x;
  const int r0 = blockIdx.x * FRB;

  for (int i = tid; i < 32*17; i += 256){
    int a = i/17, b = i - 17*a;
    S.cs[a][b] = g_cs32[a][b];
  }
  for (int i = tid; i < FRB*KPAD; i += 256){
    int f = i / KPAD, k = i - f*KPAD;
    if (k < NF){
      int idx = (r0 + f)*NF + k;
      float  m = g_mag[idx];
      float2 a = g_ang[idx];
      S.u.P[k][f] = make_float2(m * a.x, m * a.y);
    } else S.u.P[k][f] = make_float2(0.f, 0.f);
  }
  __syncthreads();

  // stage I1: H[q][m] = sum_{k==m mod 32} T[q][k]*P[k]  (k ascending)
  for (int i = tid; i < 25*32; i += 256){
    int q = i >> 5, m = i & 31;
    float hr[FRB], hi[FRB];
#pragma unroll
    for (int f = 0; f < FRB; f++){ hr[f] = 0.f; hi[f] = 0.f; }
#pragma unroll
    for (int j = 0; j < 13; j++){
      int k = m + (j << 5);
      float2 t = g_TI[q][k];
      float4 p01 = *(const float4*)&S.u.P[k][0];   // frames 0,1
      float4 p23 = *(const float4*)&S.u.P[k][2];   // frames 2,3
      float px[FRB] = {p01.x, p01.z, p23.x, p23.z};
      float py[FRB] = {p01.y, p01.w, p23.y, p23.w};
#pragma unroll
      for (int f = 0; f < FRB; f++){
        hr[f] = fmaf(t.x, px[f], hr[f]); hr[f] = fmaf(-t.y, py[f], hr[f]);
        hi[f] = fmaf(t.x, py[f], hi[f]); hi[f] = fmaf( t.y, px[f], hi[f]);
      }
    }
#pragma unroll
    for (int f = 0; f < FRB; f++)
      S.H[f][q][m] = make_float2(hr[f], hi[f]);
  }
  __syncthreads();

  // fold m <-> 32-m (real extraction); overlays dead P
  for (int i = tid; i < FRB*17*25; i += 256){
    int f = i / 425, rem = i - f*425;
    int m = rem / 25, q = rem - 25*m;
    float a, b;
    if (m == 0)      { a = S.H[f][q][0].x;  b = 0.f; }
    else if (m == 16){ a = S.H[f][q][16].x; b = 0.f; }
    else {
      float2 h0 = S.H[f][q][m], h1 = S.H[f][q][32-m];
      a = h0.x + h1.x;
      b = h1.y - h0.y;
    }
    S.u.AB[f][m][q] = make_float2(a, b);
  }
  __syncthreads();

  // stage I2 + window (win via L1-cached global)
  for (int i = tid; i < FRB*NFFT; i += 256){
    int f = i / NFFT, n = i - f*NFFT;
    int p = n / 25, q = n - 25*p;
    float xv = 0.f;
#pragma unroll
    for (int m = 0; m <= 16; m++){
      float2 ab = S.u.AB[f][m][q];
      float2 cs = S.cs[p][m];
      xv = fmaf(ab.x, cs.x, xv);
      xv = fmaf(ab.y, cs.y, xv);
    }
    g_fr[(r0 + f)*NFFT + n] = xv * g_win[n];
  }
}

// ------------------------- CT stft + GL update (frame-contiguous G) ----------
struct __align__(16) StftS {
  float  fS[FRB][NFFT];            // 12.8 KB
  float2 uv[FRB][17][25];          // (u, v)                   13.6 KB
  float2 G [25][17][FRB];          // (Gr, -gi), f contiguous  13.6 KB
  float2 cs[32][17];               //                           4.3 KB
};

__global__ __launch_bounds__(256)
void k_stft(){
  __shared__ StftS S;
  const int tid = threadIdx.x;
  const int r0 = blockIdx.x * FRB;

  for (int i = tid; i < 32*17; i += 256){
    int a = i/17, c = i - 17*a;
    S.cs[a][c] = g_cs32[a][c];
  }
  // reflect-pad gather * window
  for (int i = tid; i < FRB*NFFT; i += 256){
    int f = i / NFFT, n = i - f*NFFT;
    int r = r0 + f, b = r >> 9, t = r & 511;
    int s = t*200 + n - 400;
    if (s < 0) s = -s;
    else if (s >= LOUT) s = 2*LOUT - 2 - s;
    S.fS[f][n] = g_inv[b*LOUT + s] * g_win[n];
  }
  __syncthreads();

  // fold p <-> 32-p (real input)
  for (int i = tid; i < FRB*17*25; i += 256){
    int f = i / 425, rem = i - f*425;
    int p = rem / 25, q = rem - 25*p;
    float u, v;
    if (p == 0)      { u = S.fS[f][q];       v = 0.f; }
    else if (p == 16){ u = S.fS[f][400 + q]; v = 0.f; }
    else { float a = S.fS[f][25*p + q], cc = S.fS[f][25*(32-p) + q];
           u = a + cc; v = a - cc; }
    S.uv[f][p][q] = make_float2(u, v);
  }
  __syncthreads();

  // stage F1  (writes f-contiguous G)
  for (int i = tid; i < FRB*25*17; i += 256){
    int f = i / 425, rem = i - f*425;
    int q = rem / 17, m = rem - 17*q;
    float gr = 0.f, gi = 0.f;
#pragma unroll
    for (int p = 0; p <= 16; p++){
      float2 uv = S.uv[f][p][q];
      float2 cs = S.cs[m][p];
      gr = fmaf(uv.x, cs.x, gr);
      gi = fmaf(uv.y, cs.y, gi);
    }
    S.G[q][m][f] = make_float2(gr, -gi);
  }
  __syncthreads();

  // stage F2 + momentum + phase normalize (LDS.128 over frames)
  for (int k = tid; k < NF; k += 256){
    int m = k & 31;
    int mm = (m <= 16) ? m : 32 - m;
    float sg = (m <= 16) ? 1.f : -1.f;
    float xr[FRB], xi[FRB];
#pragma unroll
    for (int f = 0; f < FRB; f++){ xr[f] = 0.f; xi[f] = 0.f; }
#pragma unroll 5
    for (int q = 0; q < 25; q++){
      float2 t = g_TF[q][k];
      float4 g01 = *(const float4*)&S.G[q][mm][0];   // frames 0,1
      float4 g23 = *(const float4*)&S.G[q][mm][2];   // frames 2,3
      float gx[FRB] = {g01.x, g01.z, g23.x, g23.z};
      float gy[FRB] = {g01.y, g01.w, g23.y, g23.w};
#pragma unroll
      for (int f = 0; f < FRB; f++){
        float grv = gx[f], giv = sg * gy[f];
        xr[f] = fmaf(t.x, grv, xr[f]); xr[f] = fmaf(t.y, giv, xr[f]);
        xi[f] = fmaf(t.x, giv, xi[f]); xi[f] = fmaf(-t.y, grv, xi[f]);
      }
    }
#pragma unroll
    for (int f = 0; f < FRB; f++){
      int idx = (r0 + f)*NF + k;
      float2 tp = g_t[idx];
      float nR = xr[f] - 0.49748743718592965f * tp.x;   // 0.99/1.99
      float nI = xi[f] - 0.49748743718592965f * tp.y;
      float d = sqrtf(nR*nR + nI*nI) + 1e-16f;
      g_ang[idx] = make_float2(nR / d, nI / d);
      g_t[idx]   = make_float2(xr[f], xi[f]);
    }
  }
}

// ------------------------- elementwise kernels -------------------------------
__global__ void k_ola(){
  int i = blockIdx.x*blockDim.x + threadIdx.x;
  if (i >= NB*LOUT) return;
  int b = i / LOUT, l = i - b*LOUT;
  int j = l + 400;
  int tlo = (j >= 600) ? (j-600)/200 : 0;
  int thi = j/200; if (thi > 511) thi = 511;
  float s = 0.f;
  for (int t = tlo; t <= thi; t++)
    s += g_fr[(b*NT + t)*NFFT + (j - 200*t)];
  g_inv[i] = s * g_wsqi[j];
}

__global__ void k_peak(){
  __shared__ float sm[256];
  int b = blockIdx.x;
  float mx = 0.f;
  for (int l = threadIdx.x; l < LOUT; l += 256)
    mx = fmaxf(mx, fabsf(g_inv[b*LOUT + l]));
  sm[threadIdx.x] = mx;
  __syncthreads();
  for (int s = 128; s > 0; s >>= 1){
    if (threadIdx.x < s) sm[threadIdx.x] = fmaxf(sm[threadIdx.x], sm[threadIdx.x + s]);
    __syncthreads();
  }
  if (threadIdx.x == 0) g_peak[b] = 0.98855309465693896f / sm[0];  // 10^(-0.1/20)
}

__global__ void k_scale(float* __restrict__ out){
  int i = blockIdx.x*blockDim.x + threadIdx.x;
  if (i >= NB*LOUT) return;
  out[i] = g_inv[i] * g_peak[i / LOUT];
}

// ------------------------- host driver ---------------------------------------
extern "C" void kernel_launch(void* const* d_in, const int* in_sizes, int n_in,
                              void* d_out, int out_size){
  const float* x = (const float*)d_in[0];
  float* out = (float*)d_out;

  static int attr_done = 0;
  if (!attr_done){
    cudaFuncSetAttribute(k_mel50, cudaFuncAttributeMaxDynamicSharedMemorySize,
                         (int)sizeof(MelS));
    cudaFuncSetAttribute(k_istft, cudaFuncAttributePreferredSharedMemoryCarveout,
                         cudaSharedmemCarveoutMaxShared);
    cudaFuncSetAttribute(k_stft,  cudaFuncAttributePreferredSharedMemoryCarveout,
                         cudaSharedmemCarveoutMaxShared);
    attr_done = 1;
  }

  // JAX key derivation: key(1)=(0,1); partitionable split -> child_i = block(key,(0,i))
  unsigned a0,a1,b0,b1,r0,r1,q0,q1;
  tf_block(0u,1u, 0u,0u, a0,a1);   // k1  (inverse mel spec0)
  tf_block(0u,1u, 0u,1u, b0,b1);   // k2  (griffin-lim)
  tf_block(b0,b1, 0u,0u, r0,r1);   // kr  (angle real)
  tf_block(b0,b1, 0u,1u, q0,q1);   // ki  (angle imag)

  k_setup1<<<(NF*NMEL + 255)/256, 256>>>();
  k_setup2<<<(SET2_TOT + 255)/256, 256>>>();
  k_init<<<(NTOT + 255)/256, 256>>>(a0,a1,r0,r1,q0,q1);

  // InverseMelScale: all 50 SGD+momentum iterations in ONE launch
  k_mel50<<<ROWS/MROWS, 256, sizeof(MelS)>>>(x);

  // Griffin-Lim: 30 iterations
  for (int it = 0; it < 30; it++){
    k_istft<<<ROWS/FRB, 256>>>();
    k_ola<<<(NB*LOUT + 255)/256, 256>>>();
    k_stft<<<ROWS/FRB, 256>>>();
  }

  // final istft with converged phases
  k_istft<<<ROWS/FRB, 256>>>();
  k_ola<<<(NB*LOUT + 255)/256, 256>>>();

  // normalize to -0.1 dB peak
  k_peak <<<NB, 256>>>();
  k_scale<<<(NB*LOUT + 255)/256, 256>>>(out);
}

// round 15
// speedup vs baseline: 1.1783x; 1.1783x over previous
#include <cuda_runtime.h>
#include <stdint.h>

#define NB    8
#define NMEL  80
#define NT    512
#define NF    401
#define NFFT  800
#define LOUT  102200
#define LPAD  103000
#define ROWS  4096
#define NTOT  1642496     /* ROWS*NF  */
#define FRTOT 3276800     /* ROWS*NFFT */
#define FRB   4           /* frames per block in CT kernels */
#define KPAD  416         /* padded k extent: 32*13 */
#define BW    24          /* mel filter band width (max ~22 nonzeros) */
#define MROWS 8           /* rows per block in mega-mel */

// ------------------------- device scratch (no allocs) ------------------------
__device__ float  g_fb  [NF*NMEL];
__device__ float  g_fbT [NMEL*NF];
__device__ float  g_win [NFFT];
__device__ double g_twcD[NFFT];
__device__ double g_twsD[NFFT];
__device__ float  g_wsqi[LPAD];
__device__ float2 g_TI  [25][KPAD];  // (w/800)·(cos,sin)(2pi k q/800), 0 pad
__device__ float2 g_TF  [25][KPAD];  // (cos,sin)(2pi k q/800), 0 pad
__device__ float2 g_cs32[32][17];    // (cos,sin)(2pi a b/32)
__device__ int    g_klo [NMEL];      // first nonzero k of fb column m
__device__ float  g_fbc [NMEL][BW];  // fb[klo+j][m], zero-padded
__device__ int    g_ms  [NF];        // first nonzero m of fbT column f
__device__ float  g_fbv [NF][4];     // fbT[ms+j][f], zero-padded
__device__ float  g_spec[NTOT];
__device__ float  g_mag [NTOT];
__device__ float4 g_at  [NTOT];      // (angR, angI, tR, tI) packed
__device__ float  g_fr  [FRTOT];
__device__ float  g_inv [NB*LOUT];
__device__ float  g_peak[NB];

// ------------------------- threefry-2x32 (JAX schedule) ----------------------
__host__ __device__ inline void tf_block(unsigned k0, unsigned k1,
                                         unsigned c0, unsigned c1,
                                         unsigned &o0, unsigned &o1){
  unsigned ks2 = k0 ^ k1 ^ 0x1BD11BDAu;
  unsigned x0 = c0 + k0, x1 = c1 + k1;
#define TFR(r) { x0 += x1; x1 = (x1 << (r)) | (x1 >> (32 - (r))); x1 ^= x0; }
  TFR(13) TFR(15) TFR(26) TFR(6)  x0 += k1;  x1 += ks2 + 1u;
  TFR(17) TFR(29) TFR(16) TFR(24) x0 += ks2; x1 += k0 + 2u;
  TFR(13) TFR(15) TFR(26) TFR(6)  x0 += k0;  x1 += k1 + 3u;
  TFR(17) TFR(29) TFR(16) TFR(24) x0 += k1;  x1 += ks2 + 4u;
  TFR(13) TFR(15) TFR(26) TFR(6)  x0 += ks2; x1 += k0 + 5u;
#undef TFR
  o0 = x0; o1 = x1;
}

__device__ __forceinline__ float u01(unsigned bits){
  return __uint_as_float((bits >> 9) | 0x3f800000u) - 1.0f;
}

// ------------------------- setup kernels ------------------------------------
__global__ void k_setup1(){
  int i = blockIdx.x*blockDim.x + threadIdx.x;
  if (i < NFFT){
    g_win[i]  = (float)(0.5 - 0.5*cospi((double)i/400.0));
    g_twcD[i] = cospi((double)i/400.0);
    g_twsD[i] = sinpi((double)i/400.0);
  }
  if (i < NF*NMEL){
    int f = i / NMEL, m = i - f*NMEL;
    double freq = 10.0 * f;
    double mmax = 2595.0 * log10(1.0 + 4000.0/700.0);
    double p0 = 700.0*(pow(10.0, (mmax*(double)(m  )/81.0)/2595.0) - 1.0);
    double p1 = 700.0*(pow(10.0, (mmax*(double)(m+1)/81.0)/2595.0) - 1.0);
    double p2 = 700.0*(pow(10.0, (mmax*(double)(m+2)/81.0)/2595.0) - 1.0);
    double down = (freq - p0) / (p1 - p0);
    double up   = (p2 - freq) / (p2 - p1);
    double v = fmax(0.0, fmin(down, up));
    g_fb [f*NMEL + m] = (float)v;
    g_fbT[m*NF  + f] = (float)v;
  }
}

#define SET2_TOT (LPAD + 25*KPAD + 32*17 + NMEL + NF)
__global__ void k_setup2(){
  int i = blockIdx.x*blockDim.x + threadIdx.x;
  if (i < LPAD){
    int j = i;
    int tlo = (j >= 600) ? (j-600)/200 : 0;
    int thi = j/200; if (thi > 511) thi = 511;
    double s = 0.0;
    for (int t = tlo; t <= thi; t++){
      double w = (double)g_win[j - 200*t];
      s += w*w;
    }
    s = fmax(s, 1e-11);
    g_wsqi[j] = (float)(1.0 / s);
    return;
  }
  int ib = i - LPAD;
  if (ib < 25*KPAD){
    int q = ib / KPAD, k = ib - q*KPAD;
    if (k < NF){
      int r = (k*q) % 800;
      double c = g_twcD[r], s = g_twsD[r];
      double w = (k == 0 || k == 400) ? 1.0 : 2.0;
      g_TI[q][k] = make_float2((float)(w/800.0 * c), (float)(w/800.0 * s));
      g_TF[q][k] = make_float2((float)c, (float)s);
    } else {
      g_TI[q][k] = make_float2(0.f, 0.f);
      g_TF[q][k] = make_float2(0.f, 0.f);
    }
    return;
  }
  int ic = ib - 25*KPAD;
  if (ic < 32*17){
    int a = ic / 17, b = ic - 17*a;
    int r = (a*b) % 32;
    g_cs32[a][b] = make_float2((float)cospi((double)r/16.0),
                               (float)sinpi((double)r/16.0));
    return;
  }
  int id = ic - 32*17;
  if (id < NMEL){
    int m = id;
    int klo = 0;
    for (int k = 0; k < NF; k++)
      if (g_fb[k*NMEL + m] > 0.f){ klo = k; break; }
    g_klo[m] = klo;
    for (int j = 0; j < BW; j++){
      int k = klo + j;
      g_fbc[m][j] = (k < NF) ? g_fb[k*NMEL + m] : 0.f;
    }
    return;
  }
  int ie = id - NMEL;
  if (ie < NF){
    int f = ie;
    int ms = 0;
    for (int m = 0; m < NMEL; m++)
      if (g_fbT[m*NF + f] > 0.f){ ms = m; break; }
    g_ms[f] = ms;
    for (int j = 0; j < 4; j++){
      int m = ms + j;
      g_fbv[f][j] = (m < NMEL) ? g_fbT[m*NF + f] : 0.f;
    }
  }
}

// ------------------------- RNG init ------------------------------------------
__global__ void k_init(unsigned a0, unsigned a1, unsigned r0, unsigned r1,
                       unsigned q0, unsigned q1){
  int i = blockIdx.x*blockDim.x + threadIdx.x;
  if (i >= NTOT) return;
  unsigned o0, o1;
  tf_block(a0, a1, 0u, (unsigned)i, o0, o1);
  g_spec[i] = u01(o0 ^ o1);                     // spec0 is (B,T,F) = our layout
  // angles drawn in (B,F,T) order -> remap flat index
  int b = i / (NT*NF);
  int rem = i - b*(NT*NF);
  int t = rem / NF, f = rem - t*NF;
  unsigned j = (unsigned)(b*(NF*NT) + f*NT + t);
  unsigned p0, p1;
  tf_block(r0, r1, 0u, j, o0, o1);
  tf_block(q0, q1, 0u, j, p0, p1);
  g_at[i] = make_float4(u01(o0 ^ o1), u01(p0 ^ p1), 0.f, 0.f);
}

// ------------------------- mega mel (R12: transposed tables) -----------------
struct MelS {
  float sS[MROWS][440];   // spec rows, zero-padded k>=401
  float vS[MROWS][404];   // velocity
  float dS[MROWS][84];    // diff, zero-padded m>=80
  float xS[MROWS][80];    // mel target (cached)
  float fbcT[BW][80];     // transposed: stride-1 lane access
  float fbvT[4][404];
  int   klo[NMEL];
  int   ms[NF];
};

__global__ __launch_bounds__(256)
void k_mel50(const float* __restrict__ x){
  extern __shared__ char smraw[];
  MelS* S = (MelS*)smraw;
  const int tid = threadIdx.x;
  const int row0 = blockIdx.x * MROWS;

  for (int i = tid; i < MROWS*440; i += 256){
    int r = i / 440, k = i - r*440;
    S->sS[r][k] = (k < NF) ? g_spec[(row0 + r)*NF + k] : 0.f;
  }
  for (int i = tid; i < MROWS*404; i += 256){
    int r = i / 404, k = i - r*404;
    S->vS[r][k] = 0.f;
  }
  for (int i = tid; i < MROWS*84; i += 256){
    int r = i / 84, m = i - r*84;
    if (m >= NMEL) S->dS[r][m] = 0.f;
  }
  for (int i = tid; i < MROWS*NMEL; i += 256){
    int r = i / NMEL, m = i - r*NMEL;
    int row = row0 + r, b = row >> 9, t = row & 511;
    S->xS[r][m] = x[(b*NMEL + m)*NT + t];
  }
  for (int i = tid; i < NMEL*BW; i += 256){
    int m = i / BW, j = i - m*BW;
    S->fbcT[j][m] = g_fbc[m][j];
  }
  for (int i = tid; i < NF*4; i += 256){
    int f = i >> 2, j = i & 3;
    S->fbvT[j][f] = g_fbv[f][j];
  }
  for (int i = tid; i < NMEL; i += 256) S->klo[i] = g_klo[i];
  for (int i = tid; i < NF;   i += 256) S->ms[i]  = g_ms[i];
  __syncthreads();

#pragma unroll 1
  for (int it = 0; it < 50; it++){
    for (int i = tid; i < MROWS*NMEL; i += 256){
      int r = i / NMEL, m = i - r*NMEL;
      int klo = S->klo[m];
      float acc = 0.f;
#pragma unroll
      for (int j = 0; j < BW; j++)
        acc = fmaf(S->sS[r][klo + j], S->fbcT[j][m], acc);
      S->dS[r][m] = S->xS[r][m] - acc;
    }
    __syncthreads();
    for (int i = tid; i < MROWS*NF; i += 256){
      int r = i / NF, f = i - r*NF;
      int ms = S->ms[f];
      float acc = 0.f;
#pragma unroll
      for (int j = 0; j < 4; j++)
        acc = fmaf(S->dS[r][ms + j], S->fbvT[j][f], acc);
      float g = -0.003125f * acc;             // -2/(B*M)
      float v = 0.9f * S->vS[r][f] + g;
      S->vS[r][f] = v;
      S->sS[r][f] = fmaxf(S->sS[r][f] - 0.1f*v, 0.f);
    }
    __syncthreads();
  }

  for (int i = tid; i < MROWS*NF; i += 256){
    int r = i / NF, k = i - r*NF;
    g_mag[(row0 + r)*NF + k] = sqrtf(S->sS[r][k]);
  }
}

// ------------------------- CT istft (R13 layout + I2 conjugate pairing) ------
struct IstftS {
  union {
    float2 P [FRB][KPAD];          // (Pre, Pim)   13.3 KB   (conflict-free)
    float2 AB[FRB][17][25];        // (Aa, Bb)     13.6 KB
  } u;
  float2 H [FRB][25][32];          // (Hr, Hi)     25.6 KB
  float2 cs[32][17];               // (c32, s32)    4.3 KB
};

__global__ __launch_bounds__(256)
void k_istft(){
  __shared__ IstftS S;
  const int tid = threadIdx.x;
  const int r0 = blockIdx.x * FRB;

  for (int i = tid; i < 32*17; i += 256){
    int a = i/17, b = i - 17*a;
    S.cs[a][b] = g_cs32[a][b];
  }
  for (int i = tid; i < FRB*KPAD; i += 256){
    int f = i / KPAD, k = i - f*KPAD;
    if (k < NF){
      int idx = (r0 + f)*NF + k;
      float  m  = g_mag[idx];
      float4 at = g_at[idx];
      S.u.P[f][k] = make_float2(m * at.x, m * at.y);
    } else S.u.P[f][k] = make_float2(0.f, 0.f);
  }
  __syncthreads();

  // stage I1: H[q][m] = sum_{k==m mod 32} T[q][k]*P[k]  (k ascending)
  for (int i = tid; i < 25*32; i += 256){
    int q = i >> 5, m = i & 31;
    float hr[FRB], hi[FRB];
#pragma unroll
    for (int f = 0; f < FRB; f++){ hr[f] = 0.f; hi[f] = 0.f; }
#pragma unroll
    for (int j = 0; j < 13; j++){
      int k = m + (j << 5);
      float2 t = g_TI[q][k];
#pragma unroll
      for (int f = 0; f < FRB; f++){
        float2 p = S.u.P[f][k];
        hr[f] = fmaf(t.x, p.x, hr[f]); hr[f] = fmaf(-t.y, p.y, hr[f]);
        hi[f] = fmaf(t.x, p.y, hi[f]); hi[f] = fmaf( t.y, p.x, hi[f]);
      }
    }
#pragma unroll
    for (int f = 0; f < FRB; f++)
      S.H[f][q][m] = make_float2(hr[f], hi[f]);
  }
  __syncthreads();

  // fold m <-> 32-m (real extraction); overlays dead P
  for (int i = tid; i < FRB*17*25; i += 256){
    int f = i / 425, rem = i - f*425;
    int m = rem / 25, q = rem - 25*m;
    float a, b;
    if (m == 0)      { a = S.H[f][q][0].x;  b = 0.f; }
    else if (m == 16){ a = S.H[f][q][16].x; b = 0.f; }
    else {
      float2 h0 = S.H[f][q][m], h1 = S.H[f][q][32-m];
      a = h0.x + h1.x;
      b = h1.y - h0.y;
    }
    S.u.AB[f][m][q] = make_float2(a, b);
  }
  __syncthreads();

  // stage I2 + window, conjugate p-pairing: n1=25p+q and n2=25(32-p)+q share
  // AB and |cs| operands (cos even, sin odd in p -> bit-identical chains).
  for (int i = tid; i < FRB*17*25; i += 256){
    int f = i / 425, rem = i - f*425;
    int p = rem / 25, q = rem - 25*p;      // p in 0..16
    float xv1 = 0.f, xv2 = 0.f;
#pragma unroll
    for (int m = 0; m <= 16; m++){
      float2 ab = S.u.AB[f][m][q];
      float2 cs = S.cs[p][m];
      xv1 = fmaf(ab.x, cs.x, xv1); xv1 = fmaf(ab.y,  cs.y, xv1);
      xv2 = fmaf(ab.x, cs.x, xv2); xv2 = fmaf(ab.y, -cs.y, xv2);
    }
    int n1 = 25*p + q;
    g_fr[(r0 + f)*NFFT + n1] = xv1 * g_win[n1];
    if (p >= 1 && p <= 15){
      int n2 = 25*(32 - p) + q;
      g_fr[(r0 + f)*NFFT + n2] = xv2 * g_win[n2];
    }
  }
}

// ------------------------- CT stft + GL update (R13 layout) ------------------
struct StftS {
  float  fS[FRB][NFFT];            // 12.8 KB
  float2 uv[FRB][17][25];          // (u, v)       13.6 KB
  float2 G [FRB][25][17];          // (Gr, -gi)    13.6 KB
  float2 cs[32][17];               //               4.3 KB
};

__global__ __launch_bounds__(256)
void k_stft(){
  __shared__ StftS S;
  const int tid = threadIdx.x;
  const int r0 = blockIdx.x * FRB;

  for (int i = tid; i < 32*17; i += 256){
    int a = i/17, c = i - 17*a;
    S.cs[a][c] = g_cs32[a][c];
  }
  // reflect-pad gather * window
  for (int i = tid; i < FRB*NFFT; i += 256){
    int f = i / NFFT, n = i - f*NFFT;
    int r = r0 + f, b = r >> 9, t = r & 511;
    int s = t*200 + n - 400;
    if (s < 0) s = -s;
    else if (s >= LOUT) s = 2*LOUT - 2 - s;
    S.fS[f][n] = g_inv[b*LOUT + s] * g_win[n];
  }
  __syncthreads();

  // fold p <-> 32-p (real input)
  for (int i = tid; i < FRB*17*25; i += 256){
    int f = i / 425, rem = i - f*425;
    int p = rem / 25, q = rem - 25*p;
    float u, v;
    if (p == 0)      { u = S.fS[f][q];       v = 0.f; }
    else if (p == 16){ u = S.fS[f][400 + q]; v = 0.f; }
    else { float a = S.fS[f][25*p + q], cc = S.fS[f][25*(32-p) + q];
           u = a + cc; v = a - cc; }
    S.uv[f][p][q] = make_float2(u, v);
  }
  __syncthreads();

  // stage F1
  for (int i = tid; i < FRB*25*17; i += 256){
    int f = i / 425, rem = i - f*425;
    int q = rem / 17, m = rem - 17*q;
    float gr = 0.f, gi = 0.f;
#pragma unroll
    for (int p = 0; p <= 16; p++){
      float2 uv = S.uv[f][p][q];
      float2 cs = S.cs[m][p];
      gr = fmaf(uv.x, cs.x, gr);
      gi = fmaf(uv.y, cs.y, gi);
    }
    S.G[f][q][m] = make_float2(gr, -gi);
  }
  __syncthreads();

  // stage F2 + momentum + phase normalize (packed ang/t float4)
  for (int k = tid; k < NF; k += 256){
    int m = k & 31;
    int mm = (m <= 16) ? m : 32 - m;
    float sg = (m <= 16) ? 1.f : -1.f;
    float xr[FRB], xi[FRB];
#pragma unroll
    for (int f = 0; f < FRB; f++){ xr[f] = 0.f; xi[f] = 0.f; }
#pragma unroll 5
    for (int q = 0; q < 25; q++){
      float2 t = g_TF[q][k];
#pragma unroll
      for (int f = 0; f < FRB; f++){
        float2 g = S.G[f][q][mm];
        float grv = g.x, giv = sg * g.y;
        xr[f] = fmaf(t.x, grv, xr[f]); xr[f] = fmaf(t.y, giv, xr[f]);
        xi[f] = fmaf(t.x, giv, xi[f]); xi[f] = fmaf(-t.y, grv, xi[f]);
      }
    }
#pragma unroll
    for (int f = 0; f < FRB; f++){
      int idx = (r0 + f)*NF + k;
      float4 at = g_at[idx];
      float nR = xr[f] - 0.49748743718592965f * at.z;   // 0.99/1.99
      float nI = xi[f] - 0.49748743718592965f * at.w;
      float d = sqrtf(nR*nR + nI*nI) + 1e-16f;
      g_at[idx] = make_float4(nR / d, nI / d, xr[f], xi[f]);
    }
  }
}

// ------------------------- elementwise kernels -------------------------------
__global__ void k_ola(){
  int i = blockIdx.x*blockDim.x + threadIdx.x;
  if (i >= NB*LOUT) return;
  int b = i / LOUT, l = i - b*LOUT;
  int j = l + 400;
  int tlo = (j >= 600) ? (j-600)/200 : 0;
  int thi = j/200; if (thi > 511) thi = 511;
  float s = 0.f;
  for (int t = tlo; t <= thi; t++)
    s += g_fr[(b*NT + t)*NFFT + (j - 200*t)];
  g_inv[i] = s * g_wsqi[j];
}

__global__ void k_peak(){
  __shared__ float sm[256];
  int b = blockIdx.x;
  float mx = 0.f;
  for (int l = threadIdx.x; l < LOUT; l += 256)
    mx = fmaxf(mx, fabsf(g_inv[b*LOUT + l]));
  sm[threadIdx.x] = mx;
  __syncthreads();
  for (int s = 128; s > 0; s >>= 1){
    if (threadIdx.x < s) sm[threadIdx.x] = fmaxf(sm[threadIdx.x], sm[threadIdx.x + s]);
    __syncthreads();
  }
  if (threadIdx.x == 0) g_peak[b] = 0.98855309465693896f / sm[0];  // 10^(-0.1/20)
}

__global__ void k_scale(float* __restrict__ out){
  int i = blockIdx.x*blockDim.x + threadIdx.x;
  if (i >= NB*LOUT) return;
  out[i] = g_inv[i] * g_peak[i / LOUT];
}

// ------------------------- host driver ---------------------------------------
extern "C" void kernel_launch(void* const* d_in, const int* in_sizes, int n_in,
                              void* d_out, int out_size){
  const float* x = (const float*)d_in[0];
  float* out = (float*)d_out;

  static int attr_done = 0;
  if (!attr_done){
    cudaFuncSetAttribute(k_mel50, cudaFuncAttributeMaxDynamicSharedMemorySize,
                         (int)sizeof(MelS));
    cudaFuncSetAttribute(k_istft, cudaFuncAttributePreferredSharedMemoryCarveout,
                         cudaSharedmemCarveoutMaxShared);
    cudaFuncSetAttribute(k_stft,  cudaFuncAttributePreferredSharedMemoryCarveout,
                         cudaSharedmemCarveoutMaxShared);
    attr_done = 1;
  }

  // JAX key derivation: key(1)=(0,1); partitionable split -> child_i = block(key,(0,i))
  unsigned a0,a1,b0,b1,r0,r1,q0,q1;
  tf_block(0u,1u, 0u,0u, a0,a1);   // k1  (inverse mel spec0)
  tf_block(0u,1u, 0u,1u, b0,b1);   // k2  (griffin-lim)
  tf_block(b0,b1, 0u,0u, r0,r1);   // kr  (angle real)
  tf_block(b0,b1, 0u,1u, q0,q1);   // ki  (angle imag)

  k_setup1<<<(NF*NMEL + 255)/256, 256>>>();
  k_setup2<<<(SET2_TOT + 255)/256, 256>>>();
  k_init<<<(NTOT + 255)/256, 256>>>(a0,a1,r0,r1,q0,q1);

  // InverseMelScale: all 50 SGD+momentum iterations in ONE launch
  k_mel50<<<ROWS/MROWS, 256, sizeof(MelS)>>>(x);

  // Griffin-Lim: 30 iterations
  for (int it = 0; it < 30; it++){
    k_istft<<<ROWS/FRB, 256>>>();
    k_ola<<<(NB*LOUT + 255)/256, 256>>>();
    k_stft<<<ROWS/FRB, 256>>>();
  }

  // final istft with converged phases
  k_istft<<<ROWS/FRB, 256>>>();
  k_ola<<<(NB*LOUT + 255)/256, 256>>>();

  // normalize to -0.1 dB peak
  k_peak <<<NB, 256>>>();
  k_scale<<<(NB*LOUT + 255)/256, 256>>>(out);
}

// round 16
// speedup vs baseline: 1.2292x; 1.0431x over previous
#include <cuda_runtime.h>
#include <stdint.h>

#define NB    8
#define NMEL  80
#define NT    512
#define NF    401
#define NFFT  800
#define LOUT  102200
#define LPAD  103000
#define ROWS  4096
#define NTOT  1642496     /* ROWS*NF  */
#define FRTOT 3276800     /* ROWS*NFFT */
#define FRB   4           /* frames per block in CT kernels */
#define KPAD  416         /* padded k extent: 32*13 */
#define BW    24          /* mel filter band width (max ~22 nonzeros) */
#define MROWS 8           /* rows per block in mega-mel */

// ------------------------- device scratch (no allocs) ------------------------
__device__ float  g_fb  [NF*NMEL];
__device__ float  g_fbT [NMEL*NF];
__device__ float  g_win [NFFT];
__device__ double g_twcD[NFFT];
__device__ double g_twsD[NFFT];
__device__ float  g_wsqi[LPAD];
__device__ float2 g_TI  [25][KPAD];  // (w/800)·(cos,sin)(2pi k q/800), 0 pad
__device__ float2 g_TF  [25][KPAD];  // (cos,sin)(2pi k q/800), 0 pad
__device__ float2 g_cs32[32][17];    // (cos,sin)(2pi a b/32)
__device__ int    g_klo [NMEL];      // first nonzero k of fb column m
__device__ float  g_fbc [NMEL][BW];  // fb[klo+j][m], zero-padded
__device__ int    g_ms  [NF];        // first nonzero m of fbT column f
__device__ float  g_fbv [NF][4];     // fbT[ms+j][f], zero-padded
__device__ float  g_spec[NTOT];
__device__ float  g_mag [NTOT];
__device__ float4 g_at  [NTOT];      // (angR, angI, tR, tI) packed
__device__ float  g_fr  [FRTOT];
__device__ __align__(16) float g_inv [NB*LOUT];
__device__ float  g_peak[NB];

// ------------------------- threefry-2x32 (JAX schedule) ----------------------
__host__ __device__ inline void tf_block(unsigned k0, unsigned k1,
                                         unsigned c0, unsigned c1,
                                         unsigned &o0, unsigned &o1){
  unsigned ks2 = k0 ^ k1 ^ 0x1BD11BDAu;
  unsigned x0 = c0 + k0, x1 = c1 + k1;
#define TFR(r) { x0 += x1; x1 = (x1 << (r)) | (x1 >> (32 - (r))); x1 ^= x0; }
  TFR(13) TFR(15) TFR(26) TFR(6)  x0 += k1;  x1 += ks2 + 1u;
  TFR(17) TFR(29) TFR(16) TFR(24) x0 += ks2; x1 += k0 + 2u;
  TFR(13) TFR(15) TFR(26) TFR(6)  x0 += k0;  x1 += k1 + 3u;
  TFR(17) TFR(29) TFR(16) TFR(24) x0 += k1;  x1 += ks2 + 4u;
  TFR(13) TFR(15) TFR(26) TFR(6)  x0 += ks2; x1 += k0 + 5u;
#undef TFR
  o0 = x0; o1 = x1;
}

__device__ __forceinline__ float u01(unsigned bits){
  return __uint_as_float((bits >> 9) | 0x3f800000u) - 1.0f;
}

// ------------------------- setup kernels ------------------------------------
__global__ void k_setup1(){
  int i = blockIdx.x*blockDim.x + threadIdx.x;
  if (i < NFFT){
    g_win[i]  = (float)(0.5 - 0.5*cospi((double)i/400.0));
    g_twcD[i] = cospi((double)i/400.0);
    g_twsD[i] = sinpi((double)i/400.0);
  }
  if (i < NF*NMEL){
    int f = i / NMEL, m = i - f*NMEL;
    double freq = 10.0 * f;
    double mmax = 2595.0 * log10(1.0 + 4000.0/700.0);
    double p0 = 700.0*(pow(10.0, (mmax*(double)(m  )/81.0)/2595.0) - 1.0);
    double p1 = 700.0*(pow(10.0, (mmax*(double)(m+1)/81.0)/2595.0) - 1.0);
    double p2 = 700.0*(pow(10.0, (mmax*(double)(m+2)/81.0)/2595.0) - 1.0);
    double down = (freq - p0) / (p1 - p0);
    double up   = (p2 - freq) / (p2 - p1);
    double v = fmax(0.0, fmin(down, up));
    g_fb [f*NMEL + m] = (float)v;
    g_fbT[m*NF  + f] = (float)v;
  }
}

#define SET2_TOT (LPAD + 25*KPAD + 32*17 + NMEL + NF)
__global__ void k_setup2(){
  int i = blockIdx.x*blockDim.x + threadIdx.x;
  if (i < LPAD){
    int j = i;
    int tlo = (j >= 600) ? (j-600)/200 : 0;
    int thi = j/200; if (thi > 511) thi = 511;
    double s = 0.0;
    for (int t = tlo; t <= thi; t++){
      double w = (double)g_win[j - 200*t];
      s += w*w;
    }
    s = fmax(s, 1e-11);
    g_wsqi[j] = (float)(1.0 / s);
    return;
  }
  int ib = i - LPAD;
  if (ib < 25*KPAD){
    int q = ib / KPAD, k = ib - q*KPAD;
    if (k < NF){
      int r = (k*q) % 800;
      double c = g_twcD[r], s = g_twsD[r];
      double w = (k == 0 || k == 400) ? 1.0 : 2.0;
      g_TI[q][k] = make_float2((float)(w/800.0 * c), (float)(w/800.0 * s));
      g_TF[q][k] = make_float2((float)c, (float)s);
    } else {
      g_TI[q][k] = make_float2(0.f, 0.f);
      g_TF[q][k] = make_float2(0.f, 0.f);
    }
    return;
  }
  int ic = ib - 25*KPAD;
  if (ic < 32*17){
    int a = ic / 17, b = ic - 17*a;
    int r = (a*b) % 32;
    g_cs32[a][b] = make_float2((float)cospi((double)r/16.0),
                               (float)sinpi((double)r/16.0));
    return;
  }
  int id = ic - 32*17;
  if (id < NMEL){
    int m = id;
    int klo = 0;
    for (int k = 0; k < NF; k++)
      if (g_fb[k*NMEL + m] > 0.f){ klo = k; break; }
    g_klo[m] = klo;
    for (int j = 0; j < BW; j++){
      int k = klo + j;
      g_fbc[m][j] = (k < NF) ? g_fb[k*NMEL + m] : 0.f;
    }
    return;
  }
  int ie = id - NMEL;
  if (ie < NF){
    int f = ie;
    int ms = 0;
    for (int m = 0; m < NMEL; m++)
      if (g_fbT[m*NF + f] > 0.f){ ms = m; break; }
    g_ms[f] = ms;
    for (int j = 0; j < 4; j++){
      int m = ms + j;
      g_fbv[f][j] = (m < NMEL) ? g_fbT[m*NF + f] : 0.f;
    }
  }
}

// ------------------------- RNG init ------------------------------------------
__global__ void k_init(unsigned a0, unsigned a1, unsigned r0, unsigned r1,
                       unsigned q0, unsigned q1){
  int i = blockIdx.x*blockDim.x + threadIdx.x;
  if (i >= NTOT) return;
  unsigned o0, o1;
  tf_block(a0, a1, 0u, (unsigned)i, o0, o1);
  g_spec[i] = u01(o0 ^ o1);                     // spec0 is (B,T,F) = our layout
  // angles drawn in (B,F,T) order -> remap flat index
  int b = i / (NT*NF);
  int rem = i - b*(NT*NF);
  int t = rem / NF, f = rem - t*NF;
  unsigned j = (unsigned)(b*(NF*NT) + f*NT + t);
  unsigned p0, p1;
  tf_block(r0, r1, 0u, j, o0, o1);
  tf_block(q0, q1, 0u, j, p0, p1);
  g_at[i] = make_float4(u01(o0 ^ o1), u01(p0 ^ p1), 0.f, 0.f);
}

// ------------------------- mega mel (R12: transposed tables) -----------------
struct MelS {
  float sS[MROWS][440];   // spec rows, zero-padded k>=401
  float vS[MROWS][404];   // velocity
  float dS[MROWS][84];    // diff, zero-padded m>=80
  float xS[MROWS][80];    // mel target (cached)
  float fbcT[BW][80];     // transposed: stride-1 lane access
  float fbvT[4][404];
  int   klo[NMEL];
  int   ms[NF];
};

__global__ __launch_bounds__(256)
void k_mel50(const float* __restrict__ x){
  extern __shared__ char smraw[];
  MelS* S = (MelS*)smraw;
  const int tid = threadIdx.x;
  const int row0 = blockIdx.x * MROWS;

  for (int i = tid; i < MROWS*440; i += 256){
    int r = i / 440, k = i - r*440;
    S->sS[r][k] = (k < NF) ? g_spec[(row0 + r)*NF + k] : 0.f;
  }
  for (int i = tid; i < MROWS*404; i += 256){
    int r = i / 404, k = i - r*404;
    S->vS[r][k] = 0.f;
  }
  for (int i = tid; i < MROWS*84; i += 256){
    int r = i / 84, m = i - r*84;
    if (m >= NMEL) S->dS[r][m] = 0.f;
  }
  for (int i = tid; i < MROWS*NMEL; i += 256){
    int r = i / NMEL, m = i - r*NMEL;
    int row = row0 + r, b = row >> 9, t = row & 511;
    S->xS[r][m] = x[(b*NMEL + m)*NT + t];
  }
  for (int i = tid; i < NMEL*BW; i += 256){
    int m = i / BW, j = i - m*BW;
    S->fbcT[j][m] = g_fbc[m][j];
  }
  for (int i = tid; i < NF*4; i += 256){
    int f = i >> 2, j = i & 3;
    S->fbvT[j][f] = g_fbv[f][j];
  }
  for (int i = tid; i < NMEL; i += 256) S->klo[i] = g_klo[i];
  for (int i = tid; i < NF;   i += 256) S->ms[i]  = g_ms[i];
  __syncthreads();

#pragma unroll 1
  for (int it = 0; it < 50; it++){
    for (int i = tid; i < MROWS*NMEL; i += 256){
      int r = i / NMEL, m = i - r*NMEL;
      int klo = S->klo[m];
      float acc = 0.f;
#pragma unroll
      for (int j = 0; j < BW; j++)
        acc = fmaf(S->sS[r][klo + j], S->fbcT[j][m], acc);
      S->dS[r][m] = S->xS[r][m] - acc;
    }
    __syncthreads();
    for (int i = tid; i < MROWS*NF; i += 256){
      int r = i / NF, f = i - r*NF;
      int ms = S->ms[f];
      float acc = 0.f;
#pragma unroll
      for (int j = 0; j < 4; j++)
        acc = fmaf(S->dS[r][ms + j], S->fbvT[j][f], acc);
      float g = -0.003125f * acc;             // -2/(B*M)
      float v = 0.9f * S->vS[r][f] + g;
      S->vS[r][f] = v;
      S->sS[r][f] = fmaxf(S->sS[r][f] - 0.1f*v, 0.f);
    }
    __syncthreads();
  }

  for (int i = tid; i < MROWS*NF; i += 256){
    int r = i / NF, k = i - r*NF;
    g_mag[(row0 + r)*NF + k] = sqrtf(S->sS[r][k]);
  }
}

// ------------------------- CT istft (R15 + zero-tap trim) ---------------------
struct IstftS {
  union {
    float2 P [FRB][KPAD];          // (Pre, Pim)   13.3 KB   (conflict-free)
    float2 AB[FRB][17][25];        // (Aa, Bb)     13.6 KB
  } u;
  float2 H [FRB][25][32];          // (Hr, Hi)     25.6 KB
  float2 cs[32][17];               // (c32, s32)    4.3 KB
};

__global__ __launch_bounds__(256)
void k_istft(){
  __shared__ IstftS S;
  const int tid = threadIdx.x;
  const int r0 = blockIdx.x * FRB;

  for (int i = tid; i < 32*17; i += 256){
    int a = i/17, b = i - 17*a;
    S.cs[a][b] = g_cs32[a][b];
  }
  // fill only k<NF: pad region [401,416) is never read after the tap trim
  for (int i = tid; i < FRB*NF; i += 256){
    int f = i / NF, k = i - f*NF;
    int idx = (r0 + f)*NF + k;
    float  m  = g_mag[idx];
    float4 at = g_at[idx];
    S.u.P[f][k] = make_float2(m * at.x, m * at.y);
  }
  __syncthreads();

  // stage I1: H[q][m] = sum_{k==m mod 32} T[q][k]*P[k]  (k ascending)
  // taps 0..11 for all m; tap 12 (k=m+384) only valid for m<=16 (else exact 0)
  for (int i = tid; i < 25*32; i += 256){
    int q = i >> 5, m = i & 31;
    float hr[FRB], hi[FRB];
#pragma unroll
    for (int f = 0; f < FRB; f++){ hr[f] = 0.f; hi[f] = 0.f; }
#pragma unroll
    for (int j = 0; j < 12; j++){
      int k = m + (j << 5);
      float2 t = g_TI[q][k];
#pragma unroll
      for (int f = 0; f < FRB; f++){
        float2 p = S.u.P[f][k];
        hr[f] = fmaf(t.x, p.x, hr[f]); hr[f] = fmaf(-t.y, p.y, hr[f]);
        hi[f] = fmaf(t.x, p.y, hi[f]); hi[f] = fmaf( t.y, p.x, hi[f]);
      }
    }
    if (m <= 16){
      int k = m + 384;
      float2 t = g_TI[q][k];
#pragma unroll
      for (int f = 0; f < FRB; f++){
        float2 p = S.u.P[f][k];
        hr[f] = fmaf(t.x, p.x, hr[f]); hr[f] = fmaf(-t.y, p.y, hr[f]);
        hi[f] = fmaf(t.x, p.y, hi[f]); hi[f] = fmaf( t.y, p.x, hi[f]);
      }
    }
#pragma unroll
    for (int f = 0; f < FRB; f++)
      S.H[f][q][m] = make_float2(hr[f], hi[f]);
  }
  __syncthreads();

  // fold m <-> 32-m (real extraction); overlays dead P
  for (int i = tid; i < FRB*17*25; i += 256){
    int f = i / 425, rem = i - f*425;
    int m = rem / 25, q = rem - 25*m;
    float a, b;
    if (m == 0)      { a = S.H[f][q][0].x;  b = 0.f; }
    else if (m == 16){ a = S.H[f][q][16].x; b = 0.f; }
    else {
      float2 h0 = S.H[f][q][m], h1 = S.H[f][q][32-m];
      a = h0.x + h1.x;
      b = h1.y - h0.y;
    }
    S.u.AB[f][m][q] = make_float2(a, b);
  }
  __syncthreads();

  // stage I2 + window, conjugate p-pairing: n1=25p+q and n2=25(32-p)+q share
  // AB and |cs| operands (cos even, sin odd in p -> bit-identical chains).
  for (int i = tid; i < FRB*17*25; i += 256){
    int f = i / 425, rem = i - f*425;
    int p = rem / 25, q = rem - 25*p;      // p in 0..16
    float xv1 = 0.f, xv2 = 0.f;
#pragma unroll
    for (int m = 0; m <= 16; m++){
      float2 ab = S.u.AB[f][m][q];
      float2 cs = S.cs[p][m];
      xv1 = fmaf(ab.x, cs.x, xv1); xv1 = fmaf(ab.y,  cs.y, xv1);
      xv2 = fmaf(ab.x, cs.x, xv2); xv2 = fmaf(ab.y, -cs.y, xv2);
    }
    int n1 = 25*p + q;
    g_fr[(r0 + f)*NFFT + n1] = xv1 * g_win[n1];
    if (p >= 1 && p <= 15){
      int n2 = 25*(32 - p) + q;
      g_fr[(r0 + f)*NFFT + n2] = xv2 * g_win[n2];
    }
  }
}

// ------------------------- CT stft + GL update (R15) --------------------------
struct StftS {
  float  fS[FRB][NFFT];            // 12.8 KB
  float2 uv[FRB][17][25];          // (u, v)       13.6 KB
  float2 G [FRB][25][17];          // (Gr, -gi)    13.6 KB
  float2 cs[32][17];               //               4.3 KB
};

__global__ __launch_bounds__(256)
void k_stft(){
  __shared__ StftS S;
  const int tid = threadIdx.x;
  const int r0 = blockIdx.x * FRB;

  for (int i = tid; i < 32*17; i += 256){
    int a = i/17, c = i - 17*a;
    S.cs[a][c] = g_cs32[a][c];
  }
  // reflect-pad gather * window
  for (int i = tid; i < FRB*NFFT; i += 256){
    int f = i / NFFT, n = i - f*NFFT;
    int r = r0 + f, b = r >> 9, t = r & 511;
    int s = t*200 + n - 400;
    if (s < 0) s = -s;
    else if (s >= LOUT) s = 2*LOUT - 2 - s;
    S.fS[f][n] = g_inv[b*LOUT + s] * g_win[n];
  }
  __syncthreads();

  // fold p <-> 32-p (real input)
  for (int i = tid; i < FRB*17*25; i += 256){
    int f = i / 425, rem = i - f*425;
    int p = rem / 25, q = rem - 25*p;
    float u, v;
    if (p == 0)      { u = S.fS[f][q];       v = 0.f; }
    else if (p == 16){ u = S.fS[f][400 + q]; v = 0.f; }
    else { float a = S.fS[f][25*p + q], cc = S.fS[f][25*(32-p) + q];
           u = a + cc; v = a - cc; }
    S.uv[f][p][q] = make_float2(u, v);
  }
  __syncthreads();

  // stage F1
  for (int i = tid; i < FRB*25*17; i += 256){
    int f = i / 425, rem = i - f*425;
    int q = rem / 17, m = rem - 17*q;
    float gr = 0.f, gi = 0.f;
#pragma unroll
    for (int p = 0; p <= 16; p++){
      float2 uv = S.uv[f][p][q];
      float2 cs = S.cs[m][p];
      gr = fmaf(uv.x, cs.x, gr);
      gi = fmaf(uv.y, cs.y, gi);
    }
    S.G[f][q][m] = make_float2(gr, -gi);
  }
  __syncthreads();

  // stage F2 + momentum + phase normalize (packed ang/t float4)
  for (int k = tid; k < NF; k += 256){
    int m = k & 31;
    int mm = (m <= 16) ? m : 32 - m;
    float sg = (m <= 16) ? 1.f : -1.f;
    float xr[FRB], xi[FRB];
#pragma unroll
    for (int f = 0; f < FRB; f++){ xr[f] = 0.f; xi[f] = 0.f; }
#pragma unroll 5
    for (int q = 0; q < 25; q++){
      float2 t = g_TF[q][k];
#pragma unroll
      for (int f = 0; f < FRB; f++){
        float2 g = S.G[f][q][mm];
        float grv = g.x, giv = sg * g.y;
        xr[f] = fmaf(t.x, grv, xr[f]); xr[f] = fmaf(t.y, giv, xr[f]);
        xi[f] = fmaf(t.x, giv, xi[f]); xi[f] = fmaf(-t.y, grv, xi[f]);
      }
    }
#pragma unroll
    for (int f = 0; f < FRB; f++){
      int idx = (r0 + f)*NF + k;
      float4 at = g_at[idx];
      float nR = xr[f] - 0.49748743718592965f * at.z;   // 0.99/1.99
      float nI = xi[f] - 0.49748743718592965f * at.w;
      float d = sqrtf(nR*nR + nI*nI) + 1e-16f;
      g_at[idx] = make_float4(nR / d, nI / d, xr[f], xi[f]);
    }
  }
}

// ------------------------- elementwise kernels -------------------------------
__global__ void k_ola(){
  int i4 = blockIdx.x*blockDim.x + threadIdx.x;
  if (i4 >= NB*LOUT/4) return;
  int i = i4 << 2;
  int b = i / LOUT, l = i - b*LOUT;
  float4 o;
  float* po = &o.x;
#pragma unroll
  for (int u = 0; u < 4; u++){
    int j = l + u + 400;
    int tlo = (j >= 600) ? (j-600)/200 : 0;
    int thi = j/200; if (thi > 511) thi = 511;
    float s = 0.f;
    for (int t = tlo; t <= thi; t++)
      s += g_fr[(b*NT + t)*NFFT + (j - 200*t)];
    po[u] = s * g_wsqi[j];
  }
  *(float4*)&g_inv[i] = o;
}

__global__ void k_peak(){
  __shared__ float sm[256];
  int b = blockIdx.x;
  float mx = 0.f;
  for (int l4 = threadIdx.x; l4 < LOUT/4; l4 += 256){
    float4 v = *(const float4*)&g_inv[b*LOUT + (l4 << 2)];
    mx = fmaxf(mx, fmaxf(fmaxf(fabsf(v.x), fabsf(v.y)),
                         fmaxf(fabsf(v.z), fabsf(v.w))));
  }
  sm[threadIdx.x] = mx;
  __syncthreads();
  for (int s = 128; s > 0; s >>= 1){
    if (threadIdx.x < s) sm[threadIdx.x] = fmaxf(sm[threadIdx.x], sm[threadIdx.x + s]);
    __syncthreads();
  }
  if (threadIdx.x == 0) g_peak[b] = 0.98855309465693896f / sm[0];  // 10^(-0.1/20)
}

__global__ void k_scale(float* __restrict__ out){
  int i4 = blockIdx.x*blockDim.x + threadIdx.x;
  if (i4 >= NB*LOUT/4) return;
  int i = i4 << 2;
  float pk = g_peak[i / LOUT];
  float4 v = *(const float4*)&g_inv[i];
  *(float4*)&out[i] = make_float4(v.x*pk, v.y*pk, v.z*pk, v.w*pk);
}

// ------------------------- host driver ---------------------------------------
extern "C" void kernel_launch(void* const* d_in, const int* in_sizes, int n_in,
                              void* d_out, int out_size){
  const float* x = (const float*)d_in[0];
  float* out = (float*)d_out;

  static int attr_done = 0;
  if (!attr_done){
    cudaFuncSetAttribute(k_mel50, cudaFuncAttributeMaxDynamicSharedMemorySize,
                         (int)sizeof(MelS));
    cudaFuncSetAttribute(k_istft, cudaFuncAttributePreferredSharedMemoryCarveout,
                         cudaSharedmemCarveoutMaxShared);
    cudaFuncSetAttribute(k_stft,  cudaFuncAttributePreferredSharedMemoryCarveout,
                         cudaSharedmemCarveoutMaxShared);
    attr_done = 1;
  }

  // JAX key derivation: key(1)=(0,1); partitionable split -> child_i = block(key,(0,i))
  unsigned a0,a1,b0,b1,r0,r1,q0,q1;
  tf_block(0u,1u, 0u,0u, a0,a1);   // k1  (inverse mel spec0)
  tf_block(0u,1u, 0u,1u, b0,b1);   // k2  (griffin-lim)
  tf_block(b0,b1, 0u,0u, r0,r1);   // kr  (angle real)
  tf_block(b0,b1, 0u,1u, q0,q1);   // ki  (angle imag)

  k_setup1<<<(NF*NMEL + 255)/256, 256>>>();
  k_setup2<<<(SET2_TOT + 255)/256, 256>>>();
  k_init<<<(NTOT + 255)/256, 256>>>(a0,a1,r0,r1,q0,q1);

  // InverseMelScale: all 50 SGD+momentum iterations in ONE launch
  k_mel50<<<ROWS/MROWS, 256, sizeof(MelS)>>>(x);

  // Griffin-Lim: 30 iterations
  for (int it = 0; it < 30; it++){
    k_istft<<<ROWS/FRB, 256>>>();
    k_ola<<<(NB*LOUT/4 + 255)/256, 256>>>();
    k_stft<<<ROWS/FRB, 256>>>();
  }

  // final istft with converged phases
  k_istft<<<ROWS/FRB, 256>>>();
  k_ola<<<(NB*LOUT/4 + 255)/256, 256>>>();

  // normalize to -0.1 dB peak
  k_peak <<<NB, 256>>>();
  k_scale<<<(NB*LOUT/4 + 255)/256, 256>>>(out);
}

// round 17
// speedup vs baseline: 1.2971x; 1.0553x over previous
#include <cuda_runtime.h>
#include <stdint.h>

#define NB    8
#define NMEL  80
#define NT    512
#define NF    401
#define NFFT  800
#define LOUT  102200
#define LPAD  103000
#define ROWS  4096
#define NTOT  1642496     /* ROWS*NF  */
#define FRTOT 3276800     /* ROWS*NFFT */
#define FRB   4           /* frames per block in CT kernels */
#define KPAD  416         /* padded k extent: 32*13 */
#define BW    24          /* mel filter band width (max ~22 nonzeros) */
#define MROWS 8           /* rows per block in mega-mel */

// ------------------------- device scratch (no allocs) ------------------------
__device__ double g_fpts[NMEL+2];
__device__ float  g_fb  [NF*NMEL];
__device__ float  g_fbT [NMEL*NF];
__device__ float  g_win [NFFT];
__device__ double g_twcD[NFFT];
__device__ double g_twsD[NFFT];
__device__ float  g_wsqi[LPAD];
__device__ float2 g_TI  [25][KPAD];  // (w/800)·(cos,sin)(2pi k q/800), 0 pad
__device__ float2 g_TF  [25][KPAD];  // (cos,sin)(2pi k q/800), 0 pad
__device__ float2 g_cs32[32][17];    // (cos,sin)(2pi a b/32)
__device__ int    g_klo [NMEL];      // first nonzero k of fb column m
__device__ float  g_fbc [NMEL][BW];  // fb[klo+j][m], zero-padded
__device__ int    g_ms  [NF];        // first nonzero m of fbT column f
__device__ float  g_fbv [NF][4];     // fbT[ms+j][f], zero-padded
__device__ float  g_spec[NTOT];
__device__ float  g_mag [NTOT];
__device__ float4 g_at  [NTOT];      // (angR, angI, tR, tI) packed
__device__ float  g_fr  [FRTOT];
__device__ __align__(16) float g_inv [NB*LOUT];
__device__ float  g_peak[NB];

// ------------------------- threefry-2x32 (JAX schedule) ----------------------
__host__ __device__ inline void tf_block(unsigned k0, unsigned k1,
                                         unsigned c0, unsigned c1,
                                         unsigned &o0, unsigned &o1){
  unsigned ks2 = k0 ^ k1 ^ 0x1BD11BDAu;
  unsigned x0 = c0 + k0, x1 = c1 + k1;
#define TFR(r) { x0 += x1; x1 = (x1 << (r)) | (x1 >> (32 - (r))); x1 ^= x0; }
  TFR(13) TFR(15) TFR(26) TFR(6)  x0 += k1;  x1 += ks2 + 1u;
  TFR(17) TFR(29) TFR(16) TFR(24) x0 += ks2; x1 += k0 + 2u;
  TFR(13) TFR(15) TFR(26) TFR(6)  x0 += k0;  x1 += k1 + 3u;
  TFR(17) TFR(29) TFR(16) TFR(24) x0 += k1;  x1 += ks2 + 4u;
  TFR(13) TFR(15) TFR(26) TFR(6)  x0 += ks2; x1 += k0 + 5u;
#undef TFR
  o0 = x0; o1 = x1;
}

__device__ __forceinline__ float u01(unsigned bits){
  return __uint_as_float((bits >> 9) | 0x3f800000u) - 1.0f;
}

// ------------------------- setup kernels ------------------------------------
__global__ void k_setup0(){
  int j = threadIdx.x;
  if (j < NMEL+2){
    double mmax = 2595.0 * log10(1.0 + 4000.0/700.0);
    g_fpts[j] = 700.0*(pow(10.0, (mmax*(double)j/81.0)/2595.0) - 1.0);
  }
}

__global__ void k_setup1(){
  int i = blockIdx.x*blockDim.x + threadIdx.x;
  if (i < NFFT){
    g_win[i]  = (float)(0.5 - 0.5*cospi((double)i/400.0));
    g_twcD[i] = cospi((double)i/400.0);
    g_twsD[i] = sinpi((double)i/400.0);
  }
  if (i < NF*NMEL){
    int f = i / NMEL, m = i - f*NMEL;
    double freq = 10.0 * f;
    double p0 = g_fpts[m], p1 = g_fpts[m+1], p2 = g_fpts[m+2];
    double down = (freq - p0) / (p1 - p0);
    double up   = (p2 - freq) / (p2 - p1);
    double v = fmax(0.0, fmin(down, up));
    g_fb [f*NMEL + m] = (float)v;
    g_fbT[m*NF  + f] = (float)v;
  }
}

#define SET2_TOT (LPAD + 25*KPAD + 32*17 + NMEL + NF)
__global__ void k_setup2(){
  int i = blockIdx.x*blockDim.x + threadIdx.x;
  if (i < LPAD){
    int j = i;
    int tlo = (j >= 600) ? (j-600)/200 : 0;
    int thi = j/200; if (thi > 511) thi = 511;
    double s = 0.0;
    for (int t = tlo; t <= thi; t++){
      double w = (double)g_win[j - 200*t];
      s += w*w;
    }
    s = fmax(s, 1e-11);
    g_wsqi[j] = (float)(1.0 / s);
    return;
  }
  int ib = i - LPAD;
  if (ib < 25*KPAD){
    int q = ib / KPAD, k = ib - q*KPAD;
    if (k < NF){
      int r = (k*q) % 800;
      double c = g_twcD[r], s = g_twsD[r];
      double w = (k == 0 || k == 400) ? 1.0 : 2.0;
      g_TI[q][k] = make_float2((float)(w/800.0 * c), (float)(w/800.0 * s));
      g_TF[q][k] = make_float2((float)c, (float)s);
    } else {
      g_TI[q][k] = make_float2(0.f, 0.f);
      g_TF[q][k] = make_float2(0.f, 0.f);
    }
    return;
  }
  int ic = ib - 25*KPAD;
  if (ic < 32*17){
    int a = ic / 17, b = ic - 17*a;
    int r = (a*b) % 32;
    g_cs32[a][b] = make_float2((float)cospi((double)r/16.0),
                               (float)sinpi((double)r/16.0));
    return;
  }
  int id = ic - 32*17;
  if (id < NMEL){
    int m = id;
    int klo = 0;
    for (int k = 0; k < NF; k++)
      if (g_fb[k*NMEL + m] > 0.f){ klo = k; break; }
    g_klo[m] = klo;
    for (int j = 0; j < BW; j++){
      int k = klo + j;
      g_fbc[m][j] = (k < NF) ? g_fb[k*NMEL + m] : 0.f;
    }
    return;
  }
  int ie = id - NMEL;
  if (ie < NF){
    int f = ie;
    int ms = 0;
    for (int m = 0; m < NMEL; m++)
      if (g_fbT[m*NF + f] > 0.f){ ms = m; break; }
    g_ms[f] = ms;
    for (int j = 0; j < 4; j++){
      int m = ms + j;
      g_fbv[f][j] = (m < NMEL) ? g_fbT[m*NF + f] : 0.f;
    }
  }
}

// ------------------------- RNG init ------------------------------------------
__global__ void k_init(unsigned a0, unsigned a1, unsigned r0, unsigned r1,
                       unsigned q0, unsigned q1){
  int i = blockIdx.x*blockDim.x + threadIdx.x;
  if (i >= NTOT) return;
  unsigned o0, o1;
  tf_block(a0, a1, 0u, (unsigned)i, o0, o1);
  g_spec[i] = u01(o0 ^ o1);                     // spec0 is (B,T,F) = our layout
  // angles drawn in (B,F,T) order -> remap flat index
  int b = i / (NT*NF);
  int rem = i - b*(NT*NF);
  int t = rem / NF, f = rem - t*NF;
  unsigned j = (unsigned)(b*(NF*NT) + f*NT + t);
  unsigned p0, p1;
  tf_block(r0, r1, 0u, j, o0, o1);
  tf_block(q0, q1, 0u, j, p0, p1);
  g_at[i] = make_float4(u01(o0 ^ o1), u01(p0 ^ p1), 0.f, 0.f);
}

// ------------------------- mega mel (R12: transposed tables) -----------------
struct MelS {
  float sS[MROWS][440];   // spec rows, zero-padded k>=401
  float vS[MROWS][404];   // velocity
  float dS[MROWS][84];    // diff, zero-padded m>=80
  float xS[MROWS][80];    // mel target (cached)
  float fbcT[BW][80];     // transposed: stride-1 lane access
  float fbvT[4][404];
  int   klo[NMEL];
  int   ms[NF];
};

__global__ __launch_bounds__(256)
void k_mel50(const float* __restrict__ x){
  extern __shared__ char smraw[];
  MelS* S = (MelS*)smraw;
  const int tid = threadIdx.x;
  const int row0 = blockIdx.x * MROWS;

  for (int i = tid; i < MROWS*440; i += 256){
    int r = i / 440, k = i - r*440;
    S->sS[r][k] = (k < NF) ? g_spec[(row0 + r)*NF + k] : 0.f;
  }
  for (int i = tid; i < MROWS*404; i += 256){
    int r = i / 404, k = i - r*404;
    S->vS[r][k] = 0.f;
  }
  for (int i = tid; i < MROWS*84; i += 256){
    int r = i / 84, m = i - r*84;
    if (m >= NMEL) S->dS[r][m] = 0.f;
  }
  for (int i = tid; i < MROWS*NMEL; i += 256){
    int r = i / NMEL, m = i - r*NMEL;
    int row = row0 + r, b = row >> 9, t = row & 511;
    S->xS[r][m] = x[(b*NMEL + m)*NT + t];
  }
  for (int i = tid; i < NMEL*BW; i += 256){
    int m = i / BW, j = i - m*BW;
    S->fbcT[j][m] = g_fbc[m][j];
  }
  for (int i = tid; i < NF*4; i += 256){
    int f = i >> 2, j = i & 3;
    S->fbvT[j][f] = g_fbv[f][j];
  }
  for (int i = tid; i < NMEL; i += 256) S->klo[i] = g_klo[i];
  for (int i = tid; i < NF;   i += 256) S->ms[i]  = g_ms[i];
  __syncthreads();

#pragma unroll 1
  for (int it = 0; it < 50; it++){
    for (int i = tid; i < MROWS*NMEL; i += 256){
      int r = i / NMEL, m = i - r*NMEL;
      int klo = S->klo[m];
      float acc = 0.f;
#pragma unroll
      for (int j = 0; j < BW; j++)
        acc = fmaf(S->sS[r][klo + j], S->fbcT[j][m], acc);
      S->dS[r][m] = S->xS[r][m] - acc;
    }
    __syncthreads();
    for (int i = tid; i < MROWS*NF; i += 256){
      int r = i / NF, f = i - r*NF;
      int ms = S->ms[f];
      float acc = 0.f;
#pragma unroll
      for (int j = 0; j < 4; j++)
        acc = fmaf(S->dS[r][ms + j], S->fbvT[j][f], acc);
      float g = -0.003125f * acc;             // -2/(B*M)
      float v = 0.9f * S->vS[r][f] + g;
      S->vS[r][f] = v;
      S->sS[r][f] = fmaxf(S->sS[r][f] - 0.1f*v, 0.f);
    }
    __syncthreads();
  }

  for (int i = tid; i < MROWS*NF; i += 256){
    int r = i / NF, k = i - r*NF;
    g_mag[(row0 + r)*NF + k] = sqrtf(S->sS[r][k]);
  }
}

// ------------------------- CT istft (R16) -------------------------------------
struct IstftS {
  union {
    float2 P [FRB][KPAD];          // (Pre, Pim)   13.3 KB   (conflict-free)
    float2 AB[FRB][17][25];        // (Aa, Bb)     13.6 KB
  } u;
  float2 H [FRB][25][32];          // (Hr, Hi)     25.6 KB
  float2 cs[32][17];               // (c32, s32)    4.3 KB
};

__global__ __launch_bounds__(256)
void k_istft(){
  __shared__ IstftS S;
  const int tid = threadIdx.x;
  const int r0 = blockIdx.x * FRB;

  for (int i = tid; i < 32*17; i += 256){
    int a = i/17, b = i - 17*a;
    S.cs[a][b] = g_cs32[a][b];
  }
  // fill only k<NF: pad region [401,416) is never read after the tap trim
  for (int i = tid; i < FRB*NF; i += 256){
    int f = i / NF, k = i - f*NF;
    int idx = (r0 + f)*NF + k;
    float  m  = g_mag[idx];
    float4 at = g_at[idx];
    S.u.P[f][k] = make_float2(m * at.x, m * at.y);
  }
  __syncthreads();

  // stage I1: H[q][m] = sum_{k==m mod 32} T[q][k]*P[k]  (k ascending)
  // taps 0..11 for all m; tap 12 (k=m+384) only valid for m<=16 (else exact 0)
  for (int i = tid; i < 25*32; i += 256){
    int q = i >> 5, m = i & 31;
    float hr[FRB], hi[FRB];
#pragma unroll
    for (int f = 0; f < FRB; f++){ hr[f] = 0.f; hi[f] = 0.f; }
#pragma unroll
    for (int j = 0; j < 12; j++){
      int k = m + (j << 5);
      float2 t = g_TI[q][k];
#pragma unroll
      for (int f = 0; f < FRB; f++){
        float2 p = S.u.P[f][k];
        hr[f] = fmaf(t.x, p.x, hr[f]); hr[f] = fmaf(-t.y, p.y, hr[f]);
        hi[f] = fmaf(t.x, p.y, hi[f]); hi[f] = fmaf( t.y, p.x, hi[f]);
      }
    }
    if (m <= 16){
      int k = m + 384;
      float2 t = g_TI[q][k];
#pragma unroll
      for (int f = 0; f < FRB; f++){
        float2 p = S.u.P[f][k];
        hr[f] = fmaf(t.x, p.x, hr[f]); hr[f] = fmaf(-t.y, p.y, hr[f]);
        hi[f] = fmaf(t.x, p.y, hi[f]); hi[f] = fmaf( t.y, p.x, hi[f]);
      }
    }
#pragma unroll
    for (int f = 0; f < FRB; f++)
      S.H[f][q][m] = make_float2(hr[f], hi[f]);
  }
  __syncthreads();

  // fold m <-> 32-m (real extraction); overlays dead P
  for (int i = tid; i < FRB*17*25; i += 256){
    int f = i / 425, rem = i - f*425;
    int m = rem / 25, q = rem - 25*m;
    float a, b;
    if (m == 0)      { a = S.H[f][q][0].x;  b = 0.f; }
    else if (m == 16){ a = S.H[f][q][16].x; b = 0.f; }
    else {
      float2 h0 = S.H[f][q][m], h1 = S.H[f][q][32-m];
      a = h0.x + h1.x;
      b = h1.y - h0.y;
    }
    S.u.AB[f][m][q] = make_float2(a, b);
  }
  __syncthreads();

  // stage I2 + window, conjugate p-pairing (bit-identical chains)
  for (int i = tid; i < FRB*17*25; i += 256){
    int f = i / 425, rem = i - f*425;
    int p = rem / 25, q = rem - 25*p;      // p in 0..16
    float xv1 = 0.f, xv2 = 0.f;
#pragma unroll
    for (int m = 0; m <= 16; m++){
      float2 ab = S.u.AB[f][m][q];
      float2 cs = S.cs[p][m];
      xv1 = fmaf(ab.x, cs.x, xv1); xv1 = fmaf(ab.y,  cs.y, xv1);
      xv2 = fmaf(ab.x, cs.x, xv2); xv2 = fmaf(ab.y, -cs.y, xv2);
    }
    int n1 = 25*p + q;
    g_fr[(r0 + f)*NFFT + n1] = xv1 * g_win[n1];
    if (p >= 1 && p <= 15){
      int n2 = 25*(32 - p) + q;
      g_fr[(r0 + f)*NFFT + n2] = xv2 * g_win[n2];
    }
  }
}

// ------------------------- CT stft + GL update (R16 + F1 m-pairing) ----------
struct StftS {
  float  fS[FRB][NFFT];            // 12.8 KB
  float2 uv[FRB][17][25];          // (u, v)       13.6 KB
  float2 G [FRB][25][17];          // (Gr, -gi)    13.6 KB
  float2 cs[32][17];               //               4.3 KB
};

__global__ __launch_bounds__(256)
void k_stft(){
  __shared__ StftS S;
  const int tid = threadIdx.x;
  const int r0 = blockIdx.x * FRB;

  for (int i = tid; i < 32*17; i += 256){
    int a = i/17, c = i - 17*a;
    S.cs[a][c] = g_cs32[a][c];
  }
  // reflect-pad gather * window
  for (int i = tid; i < FRB*NFFT; i += 256){
    int f = i / NFFT, n = i - f*NFFT;
    int r = r0 + f, b = r >> 9, t = r & 511;
    int s = t*200 + n - 400;
    if (s < 0) s = -s;
    else if (s >= LOUT) s = 2*LOUT - 2 - s;
    S.fS[f][n] = g_inv[b*LOUT + s] * g_win[n];
  }
  __syncthreads();

  // fold p <-> 32-p (real input)
  for (int i = tid; i < FRB*17*25; i += 256){
    int f = i / 425, rem = i - f*425;
    int p = rem / 25, q = rem - 25*p;
    float u, v;
    if (p == 0)      { u = S.fS[f][q];       v = 0.f; }
    else if (p == 16){ u = S.fS[f][400 + q]; v = 0.f; }
    else { float a = S.fS[f][25*p + q], cc = S.fS[f][25*(32-p) + q];
           u = a + cc; v = a - cc; }
    S.uv[f][p][q] = make_float2(u, v);
  }
  __syncthreads();

  // stage F1, m-paired: outputs (q,m0) and (q,m0+1) share uv reads.
  // Per-output ascending-p fmaf chains identical to the unpaired version.
  for (int i = tid; i < FRB*25*9; i += 256){
    int f = i / 225, rem = i - f*225;
    int q = rem / 9, mp = rem - 9*q;
    int m0 = mp << 1;
    if (m0 == 16){
      float gr = 0.f, gi = 0.f;
#pragma unroll
      for (int p = 0; p <= 16; p++){
        float2 uv = S.uv[f][p][q];
        float2 cs = S.cs[16][p];
        gr = fmaf(uv.x, cs.x, gr);
        gi = fmaf(uv.y, cs.y, gi);
      }
      S.G[f][q][16] = make_float2(gr, -gi);
    } else {
      int m1 = m0 + 1;
      float gr0 = 0.f, gi0 = 0.f, gr1 = 0.f, gi1 = 0.f;
#pragma unroll
      for (int p = 0; p <= 16; p++){
        float2 uv = S.uv[f][p][q];
        float2 c0 = S.cs[m0][p];
        float2 c1 = S.cs[m1][p];
        gr0 = fmaf(uv.x, c0.x, gr0); gi0 = fmaf(uv.y, c0.y, gi0);
        gr1 = fmaf(uv.x, c1.x, gr1); gi1 = fmaf(uv.y, c1.y, gi1);
      }
      S.G[f][q][m0] = make_float2(gr0, -gi0);
      S.G[f][q][m1] = make_float2(gr1, -gi1);
    }
  }
  __syncthreads();

  // stage F2 + momentum + phase normalize (packed ang/t float4)
  for (int k = tid; k < NF; k += 256){
    int m = k & 31;
    int mm = (m <= 16) ? m : 32 - m;
    float sg = (m <= 16) ? 1.f : -1.f;
    float xr[FRB], xi[FRB];
#pragma unroll
    for (int f = 0; f < FRB; f++){ xr[f] = 0.f; xi[f] = 0.f; }
#pragma unroll 5
    for (int q = 0; q < 25; q++){
      float2 t = g_TF[q][k];
#pragma unroll
      for (int f = 0; f < FRB; f++){
        float2 g = S.G[f][q][mm];
        float grv = g.x, giv = sg * g.y;
        xr[f] = fmaf(t.x, grv, xr[f]); xr[f] = fmaf(t.y, giv, xr[f]);
        xi[f] = fmaf(t.x, giv, xi[f]); xi[f] = fmaf(-t.y, grv, xi[f]);
      }
    }
#pragma unroll
    for (int f = 0; f < FRB; f++){
      int idx = (r0 + f)*NF + k;
      float4 at = g_at[idx];
      float nR = xr[f] - 0.49748743718592965f * at.z;   // 0.99/1.99
      float nI = xi[f] - 0.49748743718592965f * at.w;
      float d = sqrtf(nR*nR + nI*nI) + 1e-16f;
      g_at[idx] = make_float4(nR / d, nI / d, xr[f], xi[f]);
    }
  }
}

// ------------------------- elementwise kernels -------------------------------
__global__ void k_ola(){
  int i4 = blockIdx.x*blockDim.x + threadIdx.x;
  if (i4 >= NB*LOUT/4) return;
  int i = i4 << 2;
  int b = i / LOUT, l = i - b*LOUT;
  float4 o;
  float* po = &o.x;
#pragma unroll
  for (int u = 0; u < 4; u++){
    int j = l + u + 400;
    int tlo = (j >= 600) ? (j-600)/200 : 0;
    int thi = j/200; if (thi > 511) thi = 511;
    float s = 0.f;
    for (int t = tlo; t <= thi; t++)
      s += g_fr[(b*NT + t)*NFFT + (j - 200*t)];
    po[u] = s * g_wsqi[j];
  }
  *(float4*)&g_inv[i] = o;
}

__global__ void k_peak(){
  __shared__ float sm[256];
  int b = blockIdx.x;
  float mx = 0.f;
  for (int l4 = threadIdx.x; l4 < LOUT/4; l4 += 256){
    float4 v = *(const float4*)&g_inv[b*LOUT + (l4 << 2)];
    mx = fmaxf(mx, fmaxf(fmaxf(fabsf(v.x), fabsf(v.y)),
                         fmaxf(fabsf(v.z), fabsf(v.w))));
  }
  sm[threadIdx.x] = mx;
  __syncthreads();
  for (int s = 128; s > 0; s >>= 1){
    if (threadIdx.x < s) sm[threadIdx.x] = fmaxf(sm[threadIdx.x], sm[threadIdx.x + s]);
    __syncthreads();
  }
  if (threadIdx.x == 0) g_peak[b] = 0.98855309465693896f / sm[0];  // 10^(-0.1/20)
}

__global__ void k_scale(float* __restrict__ out){
  int i4 = blockIdx.x*blockDim.x + threadIdx.x;
  if (i4 >= NB*LOUT/4) return;
  int i = i4 << 2;
  float pk = g_peak[i / LOUT];
  float4 v = *(const float4*)&g_inv[i];
  *(float4*)&out[i] = make_float4(v.x*pk, v.y*pk, v.z*pk, v.w*pk);
}

// ------------------------- host driver ---------------------------------------
extern "C" void kernel_launch(void* const* d_in, const int* in_sizes, int n_in,
                              void* d_out, int out_size){
  const float* x = (const float*)d_in[0];
  float* out = (float*)d_out;

  static int attr_done = 0;
  if (!attr_done){
    cudaFuncSetAttribute(k_mel50, cudaFuncAttributeMaxDynamicSharedMemorySize,
                         (int)sizeof(MelS));
    cudaFuncSetAttribute(k_istft, cudaFuncAttributePreferredSharedMemoryCarveout,
                         cudaSharedmemCarveoutMaxShared);
    cudaFuncSetAttribute(k_stft,  cudaFuncAttributePreferredSharedMemoryCarveout,
                         cudaSharedmemCarveoutMaxShared);
    attr_done = 1;
  }

  // JAX key derivation: key(1)=(0,1); partitionable split -> child_i = block(key,(0,i))
  unsigned a0,a1,b0,b1,r0,r1,q0,q1;
  tf_block(0u,1u, 0u,0u, a0,a1);   // k1  (inverse mel spec0)
  tf_block(0u,1u, 0u,1u, b0,b1);   // k2  (griffin-lim)
  tf_block(b0,b1, 0u,0u, r0,r1);   // kr  (angle real)
  tf_block(b0,b1, 0u,1u, q0,q1);   // ki  (angle imag)

  k_setup0<<<1, 128>>>();
  k_setup1<<<(NF*NMEL + 255)/256, 256>>>();
  k_setup2<<<(SET2_TOT + 255)/256, 256>>>();
  k_init<<<(NTOT + 255)/256, 256>>>(a0,a1,r0,r1,q0,q1);

  // InverseMelScale: all 50 SGD+momentum iterations in ONE launch
  k_mel50<<<ROWS/MROWS, 256, sizeof(MelS)>>>(x);

  // Griffin-Lim: 30 iterations
  for (int it = 0; it < 30; it++){
    k_istft<<<ROWS/FRB, 256>>>();
    k_ola<<<(NB*LOUT/4 + 255)/256, 256>>>();
    k_stft<<<ROWS/FRB, 256>>>();
  }

  // final istft with converged phases
  k_istft<<<ROWS/FRB, 256>>>();
  k_ola<<<(NB*LOUT/4 + 255)/256, 256>>>();

  // normalize to -0.1 dB peak
  k_peak <<<NB, 256>>>();
  k_scale<<<(NB*LOUT/4 + 255)/256, 256>>>(out);
}